// round 5
// baseline (speedup 1.0000x reference)
#include <cuda_runtime.h>
#include <cuda_bf16.h>
#include <mma.h>
#include <math.h>

using namespace nvcuda;

// Problem dims
#define BB 4
#define SS 2048
#define EE 1024
#define HH 16
#define DD 64
#define FF 4096
#define MM (BB*SS)   // 8192 tokens

// ---------------- scratch (no allocations allowed) ----------------
__device__ float g_ln [MM*EE];
__device__ float g_q  [MM*EE];
__device__ float g_k  [MM*EE];
__device__ float g_v  [MM*EE];
__device__ float g_ctx[MM*EE];
__device__ float g_x1 [MM*EE];
__device__ float g_mid[(size_t)MM*FF];

// ---------------- LayerNorm: one block per row of 1024 ----------------
__global__ __launch_bounds__(256) void ln_kernel(const float* __restrict__ x,
                                                 const float* __restrict__ g,
                                                 const float* __restrict__ b,
                                                 float* __restrict__ y)
{
    int row = blockIdx.x;
    int tid = threadIdx.x;
    const float4* xr = (const float4*)(x + (size_t)row * EE);
    float4 v = xr[tid];
    float s  = v.x + v.y + v.z + v.w;
    float ss = v.x*v.x + v.y*v.y + v.z*v.z + v.w*v.w;

    __shared__ float rs[8], rss[8];
    #pragma unroll
    for (int o = 16; o > 0; o >>= 1) {
        s  += __shfl_down_sync(0xffffffffu, s,  o);
        ss += __shfl_down_sync(0xffffffffu, ss, o);
    }
    int w = tid >> 5;
    if ((tid & 31) == 0) { rs[w] = s; rss[w] = ss; }
    __syncthreads();
    __shared__ float sh_mean, sh_rstd;
    if (tid == 0) {
        float S1 = 0.f, S2 = 0.f;
        #pragma unroll
        for (int i = 0; i < 8; i++) { S1 += rs[i]; S2 += rss[i]; }
        float mean = S1 * (1.0f / EE);
        float var  = S2 * (1.0f / EE) - mean * mean;
        sh_mean = mean;
        sh_rstd = rsqrtf(var + 1e-5f);
    }
    __syncthreads();
    float mean = sh_mean, rstd = sh_rstd;
    float4 g4 = ((const float4*)g)[tid];
    float4 b4 = ((const float4*)b)[tid];
    float4 o;
    o.x = (v.x - mean) * rstd * g4.x + b4.x;
    o.y = (v.y - mean) * rstd * g4.y + b4.y;
    o.z = (v.z - mean) * rstd * g4.z + b4.z;
    o.w = (v.w - mean) * rstd * g4.w + b4.w;
    ((float4*)(y + (size_t)row * EE))[tid] = o;
}

// ---------------- TF32 GEMM: C[M,N] = A[M,K] @ W[N,K]^T ----------------
// Block tile 128x128, BK=16, 256 threads (8 warps, each 64x32 via 16x16x8 wmma)
#define GBM 128
#define GBN 128
#define GBK 16
#define GBKP 24   // smem row pitch (multiple of 8 for wmma ldm)

__global__ __launch_bounds__(256) void gemm_tf32(const float* __restrict__ A,
                                                 const float* __restrict__ W,
                                                 float* __restrict__ C,
                                                 int M, int N, int K)
{
    __shared__ float sA[GBM * GBKP];
    __shared__ float sB[GBN * GBKP];

    int tid  = threadIdx.x;
    int warp = tid >> 5;
    int wm   = warp >> 2;   // 0..1  (M dir, 64 rows each)
    int wn   = warp & 3;    // 0..3  (N dir, 32 cols each)
    int row0 = blockIdx.y * GBM;
    int col0 = blockIdx.x * GBN;

    wmma::fragment<wmma::accumulator, 16, 16, 8, float> acc[4][2];
    #pragma unroll
    for (int i = 0; i < 4; i++)
        #pragma unroll
        for (int j = 0; j < 2; j++)
            wmma::fill_fragment(acc[i][j], 0.0f);

    for (int k0 = 0; k0 < K; k0 += GBK) {
        // load 128x16 tiles of A and W (each 512 float4, 2 per thread)
        #pragma unroll
        for (int j = 0; j < 2; j++) {
            int f = tid + j * 256;
            int r = f >> 2;
            int c = (f & 3) << 2;
            float4 va = *(const float4*)&A[(size_t)(row0 + r) * K + k0 + c];
            *(float4*)&sA[r * GBKP + c] = va;
            float4 vb = *(const float4*)&W[(size_t)(col0 + r) * K + k0 + c];
            *(float4*)&sB[r * GBKP + c] = vb;
        }
        __syncthreads();

        #pragma unroll
        for (int ks = 0; ks < GBK; ks += 8) {
            wmma::fragment<wmma::matrix_a, 16, 16, 8, wmma::precision::tf32, wmma::row_major> af[4];
            wmma::fragment<wmma::matrix_b, 16, 16, 8, wmma::precision::tf32, wmma::col_major> bf[2];
            #pragma unroll
            for (int i = 0; i < 4; i++) {
                wmma::load_matrix_sync(af[i], &sA[(wm * 64 + i * 16) * GBKP + ks], GBKP);
                #pragma unroll
                for (int t = 0; t < af[i].num_elements; t++)
                    af[i].x[t] = wmma::__float_to_tf32(af[i].x[t]);
            }
            #pragma unroll
            for (int j = 0; j < 2; j++) {
                wmma::load_matrix_sync(bf[j], &sB[(wn * 32 + j * 16) * GBKP + ks], GBKP);
                #pragma unroll
                for (int t = 0; t < bf[j].num_elements; t++)
                    bf[j].x[t] = wmma::__float_to_tf32(bf[j].x[t]);
            }
            #pragma unroll
            for (int i = 0; i < 4; i++)
                #pragma unroll
                for (int j = 0; j < 2; j++)
                    wmma::mma_sync(acc[i][j], af[i], bf[j], acc[i][j]);
        }
        __syncthreads();
    }

    #pragma unroll
    for (int i = 0; i < 4; i++)
        #pragma unroll
        for (int j = 0; j < 2; j++)
            wmma::store_matrix_sync(&C[(size_t)(row0 + wm * 64 + i * 16) * N + col0 + wn * 32 + j * 16],
                                    acc[i][j], N, wmma::mem_row_major);
}

// ---------------- elementwise epilogues (ncols is power of 2) ----------------
__global__ void k_bias_add(float* __restrict__ y, const float* __restrict__ bias,
                           int n4, int cmask4)
{
    int stride = gridDim.x * blockDim.x;
    for (int i = blockIdx.x * blockDim.x + threadIdx.x; i < n4; i += stride) {
        float4 v  = ((float4*)y)[i];
        float4 b4 = ((const float4*)bias)[i & cmask4];
        v.x += b4.x; v.y += b4.y; v.z += b4.z; v.w += b4.w;
        ((float4*)y)[i] = v;
    }
}

__global__ void k_bias_res(const float* __restrict__ c, const float* __restrict__ bias,
                           const float* __restrict__ res, float* __restrict__ out,
                           int n4, int cmask4)
{
    int stride = gridDim.x * blockDim.x;
    for (int i = blockIdx.x * blockDim.x + threadIdx.x; i < n4; i += stride) {
        float4 v  = ((const float4*)c)[i];
        float4 r  = ((const float4*)res)[i];
        float4 b4 = ((const float4*)bias)[i & cmask4];
        v.x += b4.x + r.x; v.y += b4.y + r.y; v.z += b4.z + r.z; v.w += b4.w + r.w;
        ((float4*)out)[i] = v;
    }
}

__global__ void k_bias_gelu(float* __restrict__ y, const float* __restrict__ bias,
                            int n4, int cmask4)
{
    int stride = gridDim.x * blockDim.x;
    for (int i = blockIdx.x * blockDim.x + threadIdx.x; i < n4; i += stride) {
        float4 v  = ((float4*)y)[i];
        float4 b4 = ((const float4*)bias)[i & cmask4];
        float t;
        t = v.x + b4.x; v.x = t * normcdff(t);
        t = v.y + b4.y; v.y = t * normcdff(t);
        t = v.z + b4.z; v.z = t * normcdff(t);
        t = v.w + b4.w; v.w = t * normcdff(t);
        ((float4*)y)[i] = v;
    }
}

// ---------------- FP32 flash attention, causal ----------------
// grid: (S/64, H, B), 128 threads. Thread t owns q-row r=t/2, dims d0..d0+31 (d0=(t&1)*32).
// Online softmax; P kept in registers; pair exchange via shfl_xor(.,1).
#define FAP 68   // smem row pitch in floats (mult of 4)
#define FA_SMEM (3 * 64 * FAP * 4)

__global__ __launch_bounds__(128) void flash_kernel(const float* __restrict__ Q,
                                                    const float* __restrict__ K,
                                                    const float* __restrict__ V,
                                                    float* __restrict__ O)
{
    extern __shared__ float sm[];
    float* sQ = sm;
    float* sK = sm + 64 * FAP;
    float* sV = sm + 2 * 64 * FAP;

    int qt = blockIdx.x, h = blockIdx.y, b = blockIdx.z;
    int q0 = qt * 64;
    int tid = threadIdx.x;
    int r  = tid >> 1;
    int d0 = (tid & 1) * 32;

    // load Q tile, pre-scaled by 1/sqrt(D)=0.125
    size_t baseQ = ((size_t)(b * SS + q0)) * EE + h * DD;
    #pragma unroll
    for (int j = 0; j < 8; j++) {
        int f = tid + j * 128;
        int row = f >> 4, c4 = (f & 15) << 2;
        float4 v = *(const float4*)&Q[baseQ + (size_t)row * EE + c4];
        v.x *= 0.125f; v.y *= 0.125f; v.z *= 0.125f; v.w *= 0.125f;
        *(float4*)&sQ[row * FAP + c4] = v;
    }

    float m = -INFINITY, l = 0.0f;
    float o[32];
    #pragma unroll
    for (int i = 0; i < 32; i++) o[i] = 0.0f;

    int nchunks = qt + 1;   // causal: kv chunks 0..qt
    for (int ck = 0; ck < nchunks; ck++) {
        int c0 = ck * 64;
        __syncthreads();
        size_t baseK = ((size_t)(b * SS + c0)) * EE + h * DD;
        #pragma unroll
        for (int j = 0; j < 8; j++) {
            int f = tid + j * 128;
            int row = f >> 4, c4 = (f & 15) << 2;
            *(float4*)&sK[row * FAP + c4] = *(const float4*)&K[baseK + (size_t)row * EE + c4];
            *(float4*)&sV[row * FAP + c4] = *(const float4*)&V[baseK + (size_t)row * EE + c4];
        }
        __syncthreads();

        // scores for cols d0..d0+31 of row r
        float acc[32];
        #pragma unroll
        for (int i = 0; i < 32; i++) acc[i] = 0.0f;
        const float* qrow = &sQ[r * FAP];
        #pragma unroll 4
        for (int k = 0; k < 64; k += 4) {
            float4 q4 = *(const float4*)&qrow[k];
            #pragma unroll
            for (int c2 = 0; c2 < 32; c2++) {
                float4 k4 = *(const float4*)&sK[(d0 + c2) * FAP + k];
                acc[c2] += q4.x * k4.x + q4.y * k4.y + q4.z * k4.z + q4.w * k4.w;
            }
        }

        if (c0 == q0) {   // diagonal chunk: mask cols > row
            #pragma unroll
            for (int c2 = 0; c2 < 32; c2++)
                if (d0 + c2 > r) acc[c2] = -1.0e30f;
        }

        // online softmax update (pair via shfl)
        float mloc = acc[0];
        #pragma unroll
        for (int c2 = 1; c2 < 32; c2++) mloc = fmaxf(mloc, acc[c2]);
        mloc = fmaxf(mloc, __shfl_xor_sync(0xffffffffu, mloc, 1));
        float mnew  = fmaxf(m, mloc);
        float alpha = expf(m - mnew);
        float ssum = 0.0f;
        #pragma unroll
        for (int c2 = 0; c2 < 32; c2++) {
            float p = expf(acc[c2] - mnew);
            acc[c2] = p;
            ssum += p;
        }
        ssum += __shfl_xor_sync(0xffffffffu, ssum, 1);
        l = l * alpha + ssum;
        m = mnew;
        #pragma unroll
        for (int i = 0; i < 32; i++) o[i] *= alpha;

        // O += P @ V  (pa: own cols d0+c2; pb: partner cols (32-d0)+c2)
        #pragma unroll 4
        for (int c2 = 0; c2 < 32; c2++) {
            float pa = acc[c2];
            float pb = __shfl_xor_sync(0xffffffffu, pa, 1);
            const float* va = &sV[(d0 + c2) * FAP + d0];
            const float* vb = &sV[((32 - d0) + c2) * FAP + d0];
            #pragma unroll
            for (int i = 0; i < 32; i += 4) {
                float4 a4 = *(const float4*)&va[i];
                float4 b4 = *(const float4*)&vb[i];
                o[i]     += pa * a4.x + pb * b4.x;
                o[i + 1] += pa * a4.y + pb * b4.y;
                o[i + 2] += pa * a4.z + pb * b4.z;
                o[i + 3] += pa * a4.w + pb * b4.w;
            }
        }
    }

    float inv = 1.0f / l;
    size_t baseO = ((size_t)(b * SS + q0 + r)) * EE + h * DD + d0;
    #pragma unroll
    for (int i = 0; i < 32; i += 4) {
        float4 v;
        v.x = o[i] * inv; v.y = o[i + 1] * inv; v.z = o[i + 2] * inv; v.w = o[i + 3] * inv;
        *(float4*)&O[baseO + i] = v;
    }
}

// ---------------- launch ----------------
extern "C" void kernel_launch(void* const* d_in, const int* in_sizes, int n_in,
                              void* d_out, int out_size)
{
    (void)in_sizes; (void)n_in; (void)out_size;
    const float* x     = (const float*)d_in[0];
    // d_in[1] = causal mask (structure used implicitly)
    const float* ln1_g = (const float*)d_in[2];
    const float* ln1_b = (const float*)d_in[3];
    const float* Wq    = (const float*)d_in[4];
    const float* bq    = (const float*)d_in[5];
    const float* Wk    = (const float*)d_in[6];
    const float* bk    = (const float*)d_in[7];
    const float* Wv    = (const float*)d_in[8];
    const float* bv    = (const float*)d_in[9];
    const float* Wo    = (const float*)d_in[10];
    const float* bo    = (const float*)d_in[11];
    const float* ln2_g = (const float*)d_in[12];
    const float* ln2_b = (const float*)d_in[13];
    const float* W1    = (const float*)d_in[14];
    const float* b1    = (const float*)d_in[15];
    const float* W2    = (const float*)d_in[16];
    const float* b2    = (const float*)d_in[17];
    float* out = (float*)d_out;

    void* p;
    float *ln, *q, *k, *v, *ctx, *x1, *mid;
    cudaGetSymbolAddress(&p, g_ln);  ln  = (float*)p;
    cudaGetSymbolAddress(&p, g_q);   q   = (float*)p;
    cudaGetSymbolAddress(&p, g_k);   k   = (float*)p;
    cudaGetSymbolAddress(&p, g_v);   v   = (float*)p;
    cudaGetSymbolAddress(&p, g_ctx); ctx = (float*)p;
    cudaGetSymbolAddress(&p, g_x1);  x1  = (float*)p;
    cudaGetSymbolAddress(&p, g_mid); mid = (float*)p;

    cudaFuncSetAttribute(flash_kernel, cudaFuncAttributeMaxDynamicSharedMemorySize, FA_SMEM);

    const int n4E = MM * EE / 4, cm4E = EE / 4 - 1;
    const int n4F = MM * FF / 4, cm4F = FF / 4 - 1;
    dim3 gE(EE / GBN, MM / GBM);
    dim3 gF(FF / GBN, MM / GBM);

    // 1) ln1
    ln_kernel<<<MM, 256>>>(x, ln1_g, ln1_b, ln);
    // 2) QKV projections
    gemm_tf32<<<gE, 256>>>(ln, Wq, q, MM, EE, EE);
    gemm_tf32<<<gE, 256>>>(ln, Wk, k, MM, EE, EE);
    gemm_tf32<<<gE, 256>>>(ln, Wv, v, MM, EE, EE);
    k_bias_add<<<1024, 256>>>(q, bq, n4E, cm4E);
    k_bias_add<<<1024, 256>>>(k, bk, n4E, cm4E);
    k_bias_add<<<1024, 256>>>(v, bv, n4E, cm4E);
    // 3) attention
    flash_kernel<<<dim3(SS / 64, HH, BB), 128, FA_SMEM>>>(q, k, v, ctx);
    // 4) output projection + residual -> x1
    gemm_tf32<<<gE, 256>>>(ctx, Wo, ln, MM, EE, EE);
    k_bias_res<<<1024, 256>>>(ln, bo, x, x1, n4E, cm4E);
    // 5) ln2 (reuse k buffer)
    ln_kernel<<<MM, 256>>>(x1, ln2_g, ln2_b, k);
    // 6) FFN
    gemm_tf32<<<gF, 256>>>(k, W1, mid, MM, FF, EE);
    k_bias_gelu<<<2048, 256>>>(mid, b1, n4F, cm4F);
    gemm_tf32<<<gE, 256>>>(mid, W2, ln, MM, EE, FF);
    k_bias_res<<<1024, 256>>>(ln, b2, x1, out, n4E, cm4E);
}

// round 8
// speedup vs baseline: 1.3633x; 1.3633x over previous
#include <cuda_runtime.h>
#include <cuda_bf16.h>
#include <mma.h>
#include <math.h>
#include <cstdint>
#include <cstddef>

using namespace nvcuda;

// Problem dims
#define BB 4
#define SS 2048
#define EE 1024
#define HH 16
#define DD 64
#define FF 4096
#define MM (BB*SS)   // 8192 tokens

// ---------------- scratch (no allocations allowed) ----------------
__device__ float g_ln [MM*EE];
__device__ float g_q  [MM*EE];
__device__ float g_k  [MM*EE];
__device__ float g_v  [MM*EE];
__device__ float g_ctx[MM*EE];
__device__ float g_x1 [MM*EE];
__device__ float g_mid[(size_t)MM*FF];

// ---------------- LayerNorm: one block per row of 1024 ----------------
__global__ __launch_bounds__(256) void ln_kernel(const float* __restrict__ x,
                                                 const float* __restrict__ g,
                                                 const float* __restrict__ b,
                                                 float* __restrict__ y)
{
    int row = blockIdx.x;
    int tid = threadIdx.x;
    const float4* xr = (const float4*)(x + (size_t)row * EE);
    float4 v = xr[tid];
    float s  = v.x + v.y + v.z + v.w;
    float ss = v.x*v.x + v.y*v.y + v.z*v.z + v.w*v.w;

    __shared__ float rs[8], rss[8];
    #pragma unroll
    for (int o = 16; o > 0; o >>= 1) {
        s  += __shfl_down_sync(0xffffffffu, s,  o);
        ss += __shfl_down_sync(0xffffffffu, ss, o);
    }
    int w = tid >> 5;
    if ((tid & 31) == 0) { rs[w] = s; rss[w] = ss; }
    __syncthreads();
    __shared__ float sh_mean, sh_rstd;
    if (tid == 0) {
        float S1 = 0.f, S2 = 0.f;
        #pragma unroll
        for (int i = 0; i < 8; i++) { S1 += rs[i]; S2 += rss[i]; }
        float mean = S1 * (1.0f / EE);
        float var  = S2 * (1.0f / EE) - mean * mean;
        sh_mean = mean;
        sh_rstd = rsqrtf(var + 1e-5f);
    }
    __syncthreads();
    float mean = sh_mean, rstd = sh_rstd;
    float4 g4 = ((const float4*)g)[tid];
    float4 b4 = ((const float4*)b)[tid];
    float4 o;
    o.x = (v.x - mean) * rstd * g4.x + b4.x;
    o.y = (v.y - mean) * rstd * g4.y + b4.y;
    o.z = (v.z - mean) * rstd * g4.z + b4.z;
    o.w = (v.w - mean) * rstd * g4.w + b4.w;
    ((float4*)(y + (size_t)row * EE))[tid] = o;
}

// =====================================================================
// TF32 GEMM v2: C[M,N] = A[M,K] @ W[N,K]^T  (+ fused epilogue)
// 128x128 block tile, BK=32, cp.async double buffer, 256 threads.
// EPI: 0 = +bias   1 = +bias +res   2 = gelu(+bias)
// =====================================================================
#define Bb 128
#define Bn 128
#define Bk 32
#define BKP 40                   // smem K pitch (floats)
#define STAGE_A (Bb*BKP)         // 5120 floats
#define STAGE_SZ (2*STAGE_A)     // A+B: 10240 floats
#define EPIP 132                 // epilogue smem pitch
#define GEMM_SMEM (2*STAGE_SZ*4) // 81920 bytes (>= 128*EPIP*4 = 67584)

__device__ __forceinline__ void cp_async16(float* dst, const float* src) {
    unsigned s = (unsigned)__cvta_generic_to_shared(dst);
    asm volatile("cp.async.cg.shared.global [%0], [%1], 16;\n" :: "r"(s), "l"(src));
}

template<int EPI>
__global__ __launch_bounds__(256) void gemm2(const float* __restrict__ A,
                                             const float* __restrict__ W,
                                             const float* __restrict__ bias,
                                             const float* __restrict__ res,
                                             float* __restrict__ C,
                                             int M, int N, int K)
{
    extern __shared__ float sm[];
    int tid  = threadIdx.x;
    int warp = tid >> 5;
    int wm   = warp >> 2;   // 0..1
    int wn   = warp & 3;    // 0..3
    int row0 = blockIdx.y * Bb;
    int col0 = blockIdx.x * Bn;

    wmma::fragment<wmma::accumulator, 16, 16, 8, float> acc[4][2];
    #pragma unroll
    for (int i = 0; i < 4; i++)
        #pragma unroll
        for (int j = 0; j < 2; j++)
            wmma::fill_fragment(acc[i][j], 0.0f);

    int ntiles = K / Bk;

    // per-thread cp.async coordinates: 4 chunks of 16B for A, 4 for B per stage
    int lr[4], lc[4];
    #pragma unroll
    for (int j = 0; j < 4; j++) {
        int idx = tid + j * 256;
        lr[j] = idx >> 3;           // 0..127
        lc[j] = (idx & 7) << 2;     // 0,4,...,28
    }

    auto load_stage = [&](int s, int k0) {
        float* sA = sm + s * STAGE_SZ;
        float* sB = sA + STAGE_A;
        #pragma unroll
        for (int j = 0; j < 4; j++) {
            cp_async16(&sA[lr[j] * BKP + lc[j]], &A[(size_t)(row0 + lr[j]) * K + k0 + lc[j]]);
            cp_async16(&sB[lr[j] * BKP + lc[j]], &W[(size_t)(col0 + lr[j]) * K + k0 + lc[j]]);
        }
        asm volatile("cp.async.commit_group;\n" ::: "memory");
    };

    load_stage(0, 0);

    for (int t = 0; t < ntiles; t++) {
        if (t + 1 < ntiles) {
            load_stage((t + 1) & 1, (t + 1) * Bk);
            asm volatile("cp.async.wait_group 1;\n" ::: "memory");
        } else {
            asm volatile("cp.async.wait_group 0;\n" ::: "memory");
        }
        __syncthreads();

        float* sA = sm + (t & 1) * STAGE_SZ;
        float* sB = sA + STAGE_A;

        #pragma unroll
        for (int ks = 0; ks < Bk; ks += 8) {
            wmma::fragment<wmma::matrix_a, 16, 16, 8, wmma::precision::tf32, wmma::row_major> af[4];
            wmma::fragment<wmma::matrix_b, 16, 16, 8, wmma::precision::tf32, wmma::col_major> bf[2];
            #pragma unroll
            for (int i = 0; i < 4; i++) {
                wmma::load_matrix_sync(af[i], &sA[(wm * 64 + i * 16) * BKP + ks], BKP);
                #pragma unroll
                for (int e = 0; e < af[i].num_elements; e++)
                    af[i].x[e] = wmma::__float_to_tf32(af[i].x[e]);
            }
            #pragma unroll
            for (int j = 0; j < 2; j++) {
                wmma::load_matrix_sync(bf[j], &sB[(wn * 32 + j * 16) * BKP + ks], BKP);
                #pragma unroll
                for (int e = 0; e < bf[j].num_elements; e++)
                    bf[j].x[e] = wmma::__float_to_tf32(bf[j].x[e]);
            }
            #pragma unroll
            for (int i = 0; i < 4; i++)
                #pragma unroll
                for (int j = 0; j < 2; j++)
                    wmma::mma_sync(acc[i][j], af[i], bf[j], acc[i][j]);
        }
        __syncthreads();
    }

    // ---- fused epilogue through smem staging ----
    float* sC = sm;
    #pragma unroll
    for (int i = 0; i < 4; i++)
        #pragma unroll
        for (int j = 0; j < 2; j++)
            wmma::store_matrix_sync(&sC[(wm * 64 + i * 16) * EPIP + wn * 32 + j * 16],
                                    acc[i][j], EPIP, wmma::mem_row_major);
    __syncthreads();

    #pragma unroll
    for (int j = 0; j < 16; j++) {
        int idx = tid + j * 256;       // 4096 float4
        int r   = idx >> 5;            // 0..127
        int c4  = (idx & 31) << 2;     // 0..124
        float4 v = *(float4*)&sC[r * EPIP + c4];
        float4 b4 = *(const float4*)&bias[col0 + c4];
        v.x += b4.x; v.y += b4.y; v.z += b4.z; v.w += b4.w;
        if (EPI == 1) {
            float4 r4 = *(const float4*)&res[(size_t)(row0 + r) * N + col0 + c4];
            v.x += r4.x; v.y += r4.y; v.z += r4.z; v.w += r4.w;
        }
        if (EPI == 2) {
            v.x = v.x * normcdff(v.x);
            v.y = v.y * normcdff(v.y);
            v.z = v.z * normcdff(v.z);
            v.w = v.w * normcdff(v.w);
        }
        *(float4*)&C[(size_t)(row0 + r) * N + col0 + c4] = v;
    }
}

// =====================================================================
// FP32 flash attention v2, causal.
// grid (S/64, H, B), 128 threads. tx=tid&7 (8 col/dim groups), ty=tid>>3
// (16 row groups of 4). Each thread: 4 q-rows x 8 score-cols, output
// 4 rows x 8 dims. K/V smem XOR-swizzled (16B chunk ^ (row>>3)) to kill
// the structural 8-row-stride bank conflict. P staged via smem,
// warp-local (row groups are warp-private) -> __syncwarp handoff.
// =====================================================================
#define FQP 68
#define FPP 76
#define OFF_Q 0
#define OFF_K (64*FQP)           // 4352
#define OFF_V (OFF_K + 64*64)    // 8448
#define OFF_P (OFF_V + 64*64)    // 12544
#define FA_SMEM ((OFF_P + 64*FPP) * 4)   // 69632 bytes

__global__ __launch_bounds__(128) void flash2(const float* __restrict__ Q,
                                              const float* __restrict__ K,
                                              const float* __restrict__ V,
                                              float* __restrict__ O)
{
    extern __shared__ float sm[];
    float* sQ = sm + OFF_Q;
    float* sK = sm + OFF_K;
    float* sV = sm + OFF_V;
    float* sP = sm + OFF_P;

    int qt = blockIdx.x, h = blockIdx.y, b = blockIdx.z;
    int q0 = qt * 64;
    int tid = threadIdx.x;
    int tx = tid & 7;        // col / dim group
    int ty = tid >> 3;       // row group (4 rows)

    // load Q tile, pre-scaled by 1/sqrt(D)=0.125
    size_t baseQ = ((size_t)(b * SS + q0)) * EE + h * DD;
    #pragma unroll
    for (int j = 0; j < 8; j++) {
        int f = tid + j * 128;
        int row = f >> 4, c4 = (f & 15) << 2;
        float4 v = *(const float4*)&Q[baseQ + (size_t)row * EE + c4];
        v.x *= 0.125f; v.y *= 0.125f; v.z *= 0.125f; v.w *= 0.125f;
        *(float4*)&sQ[row * FQP + c4] = v;
    }

    float m[4], l[4], o[4][8];
    #pragma unroll
    for (int i = 0; i < 4; i++) {
        m[i] = -INFINITY; l[i] = 0.0f;
        #pragma unroll
        for (int d = 0; d < 8; d++) o[i][d] = 0.0f;
    }

    int nchunks = qt + 1;
    for (int ck = 0; ck < nchunks; ck++) {
        int c0 = ck * 64;
        __syncthreads();
        // load K,V (swizzled: 16B chunk c16 stored at c16 ^ (row>>3))
        size_t baseK = ((size_t)(b * SS + c0)) * EE + h * DD;
        #pragma unroll
        for (int j = 0; j < 8; j++) {
            int f = tid + j * 128;
            int row = f >> 4, c16 = f & 15;
            int sw = (c16 ^ (row >> 3)) << 2;
            *(float4*)&sK[row * 64 + sw] = *(const float4*)&K[baseK + (size_t)row * EE + (c16 << 2)];
            *(float4*)&sV[row * 64 + sw] = *(const float4*)&V[baseK + (size_t)row * EE + (c16 << 2)];
        }
        __syncthreads();

        // ---- scores: acc[i][j] = q-row (ty*4+i) . k-row (tx*8+j) ----
        float acc[4][8];
        #pragma unroll
        for (int i = 0; i < 4; i++)
            #pragma unroll
            for (int j = 0; j < 8; j++) acc[i][j] = 0.0f;

        #pragma unroll 4
        for (int k = 0; k < 64; k += 4) {
            float4 q4[4];
            #pragma unroll
            for (int i = 0; i < 4; i++)
                q4[i] = *(const float4*)&sQ[(ty * 4 + i) * FQP + k];
            int kc = k >> 2;
            #pragma unroll
            for (int j = 0; j < 8; j++) {
                float4 k4 = *(const float4*)&sK[(tx * 8 + j) * 64 + ((kc ^ tx) << 2)];
                #pragma unroll
                for (int i = 0; i < 4; i++)
                    acc[i][j] += q4[i].x * k4.x + q4[i].y * k4.y + q4[i].z * k4.z + q4[i].w * k4.w;
            }
        }

        if (c0 == q0) {   // diagonal chunk: mask cols > row
            #pragma unroll
            for (int i = 0; i < 4; i++)
                #pragma unroll
                for (int j = 0; j < 8; j++)
                    if (tx * 8 + j > ty * 4 + i) acc[i][j] = -1.0e30f;
        }

        // ---- online softmax per row (reduce across the 8-lane group) ----
        #pragma unroll
        for (int i = 0; i < 4; i++) {
            float mloc = acc[i][0];
            #pragma unroll
            for (int j = 1; j < 8; j++) mloc = fmaxf(mloc, acc[i][j]);
            mloc = fmaxf(mloc, __shfl_xor_sync(0xffffffffu, mloc, 1));
            mloc = fmaxf(mloc, __shfl_xor_sync(0xffffffffu, mloc, 2));
            mloc = fmaxf(mloc, __shfl_xor_sync(0xffffffffu, mloc, 4));
            float mnew  = fmaxf(m[i], mloc);
            float alpha = __expf(m[i] - mnew);
            float ssum = 0.0f;
            #pragma unroll
            for (int j = 0; j < 8; j++) {
                float p = __expf(acc[i][j] - mnew);
                acc[i][j] = p;
                ssum += p;
            }
            ssum += __shfl_xor_sync(0xffffffffu, ssum, 1);
            ssum += __shfl_xor_sync(0xffffffffu, ssum, 2);
            ssum += __shfl_xor_sync(0xffffffffu, ssum, 4);
            l[i] = l[i] * alpha + ssum;
            m[i] = mnew;
            #pragma unroll
            for (int d = 0; d < 8; d++) o[i][d] *= alpha;
            // stage P row segment (warp-private rows)
            float4 p0 = make_float4(acc[i][0], acc[i][1], acc[i][2], acc[i][3]);
            float4 p1 = make_float4(acc[i][4], acc[i][5], acc[i][6], acc[i][7]);
            *(float4*)&sP[(ty * 4 + i) * FPP + tx * 8]     = p0;
            *(float4*)&sP[(ty * 4 + i) * FPP + tx * 8 + 4] = p1;
        }
        __syncwarp();

        // ---- O += P @ V : thread owns 4 rows x dims [tx*8, tx*8+8) ----
        #pragma unroll 4
        for (int cc = 0; cc < 64; cc += 4) {
            float4 p[4];
            #pragma unroll
            for (int i = 0; i < 4; i++)
                p[i] = *(const float4*)&sP[(ty * 4 + i) * FPP + cc];
            #pragma unroll
            for (int j2 = 0; j2 < 4; j2++) {
                int c = cc + j2;
                int s = c >> 3;
                float4 v0 = *(const float4*)&sV[c * 64 + (((tx * 2)     ^ s) << 2)];
                float4 v1 = *(const float4*)&sV[c * 64 + (((tx * 2 + 1) ^ s) << 2)];
                #pragma unroll
                for (int i = 0; i < 4; i++) {
                    float pv = ((const float*)&p[i])[j2];
                    o[i][0] += pv * v0.x; o[i][1] += pv * v0.y;
                    o[i][2] += pv * v0.z; o[i][3] += pv * v0.w;
                    o[i][4] += pv * v1.x; o[i][5] += pv * v1.y;
                    o[i][6] += pv * v1.z; o[i][7] += pv * v1.w;
                }
            }
        }
    }

    // ---- write out ----
    #pragma unroll
    for (int i = 0; i < 4; i++) {
        float inv = 1.0f / l[i];
        size_t baseO = ((size_t)(b * SS + q0 + ty * 4 + i)) * EE + h * DD + tx * 8;
        float4 v0, v1;
        v0.x = o[i][0] * inv; v0.y = o[i][1] * inv; v0.z = o[i][2] * inv; v0.w = o[i][3] * inv;
        v1.x = o[i][4] * inv; v1.y = o[i][5] * inv; v1.z = o[i][6] * inv; v1.w = o[i][7] * inv;
        *(float4*)&O[baseO]     = v0;
        *(float4*)&O[baseO + 4] = v1;
    }
}

// ---------------- launch ----------------
extern "C" void kernel_launch(void* const* d_in, const int* in_sizes, int n_in,
                              void* d_out, int out_size)
{
    (void)in_sizes; (void)n_in; (void)out_size;
    const float* x     = (const float*)d_in[0];
    const float* ln1_g = (const float*)d_in[2];
    const float* ln1_b = (const float*)d_in[3];
    const float* Wq    = (const float*)d_in[4];
    const float* bq    = (const float*)d_in[5];
    const float* Wk    = (const float*)d_in[6];
    const float* bk    = (const float*)d_in[7];
    const float* Wv    = (const float*)d_in[8];
    const float* bv    = (const float*)d_in[9];
    const float* Wo    = (const float*)d_in[10];
    const float* bo    = (const float*)d_in[11];
    const float* ln2_g = (const float*)d_in[12];
    const float* ln2_b = (const float*)d_in[13];
    const float* W1    = (const float*)d_in[14];
    const float* b1    = (const float*)d_in[15];
    const float* W2    = (const float*)d_in[16];
    const float* b2    = (const float*)d_in[17];
    float* out = (float*)d_out;

    void* p;
    float *ln, *q, *k, *v, *ctx, *x1, *mid;
    cudaGetSymbolAddress(&p, g_ln);  ln  = (float*)p;
    cudaGetSymbolAddress(&p, g_q);   q   = (float*)p;
    cudaGetSymbolAddress(&p, g_k);   k   = (float*)p;
    cudaGetSymbolAddress(&p, g_v);   v   = (float*)p;
    cudaGetSymbolAddress(&p, g_ctx); ctx = (float*)p;
    cudaGetSymbolAddress(&p, g_x1);  x1  = (float*)p;
    cudaGetSymbolAddress(&p, g_mid); mid = (float*)p;

    cudaFuncSetAttribute(gemm2<0>, cudaFuncAttributeMaxDynamicSharedMemorySize, GEMM_SMEM);
    cudaFuncSetAttribute(gemm2<1>, cudaFuncAttributeMaxDynamicSharedMemorySize, GEMM_SMEM);
    cudaFuncSetAttribute(gemm2<2>, cudaFuncAttributeMaxDynamicSharedMemorySize, GEMM_SMEM);
    cudaFuncSetAttribute(flash2,   cudaFuncAttributeMaxDynamicSharedMemorySize, FA_SMEM);

    dim3 gE(EE / Bn, MM / Bb);   // (8, 64)
    dim3 gF(FF / Bn, MM / Bb);   // (32, 64)

    // 1) ln1
    ln_kernel<<<MM, 256>>>(x, ln1_g, ln1_b, ln);
    // 2) QKV projections (+bias fused)
    gemm2<0><<<gE, 256, GEMM_SMEM>>>(ln, Wq, bq, nullptr, q, MM, EE, EE);
    gemm2<0><<<gE, 256, GEMM_SMEM>>>(ln, Wk, bk, nullptr, k, MM, EE, EE);
    gemm2<0><<<gE, 256, GEMM_SMEM>>>(ln, Wv, bv, nullptr, v, MM, EE, EE);
    // 3) attention
    flash2<<<dim3(SS / 64, HH, BB), 128, FA_SMEM>>>(q, k, v, ctx);
    // 4) output projection + bias + residual -> x1
    gemm2<1><<<gE, 256, GEMM_SMEM>>>(ctx, Wo, bo, x, x1, MM, EE, EE);
    // 5) ln2
    ln_kernel<<<MM, 256>>>(x1, ln2_g, ln2_b, ln);
    // 6) FFN: W1 + bias + gelu fused, then W2 + bias + residual fused
    gemm2<2><<<gF, 256, GEMM_SMEM>>>(ln, W1, b1, nullptr, mid, MM, FF, EE);
    gemm2<1><<<gE, 256, GEMM_SMEM>>>(mid, W2, b2, x1, out, MM, EE, FF);
}